// round 1
// baseline (speedup 1.0000x reference)
#include <cuda_runtime.h>
#include <math.h>

#define Bz   16
#define Tt   500
#define Cc   512
#define Kk   7
#define NHh  8
#define HD   64
#define HIDd 2048
#define Ll   3
#define NCb  2
#define BT   (Bz * Tt)
#define SCALE 0.125f

// ---------------- scratch (device globals; no runtime allocation) ----------
__device__ float g_a[BT * Cc];
__device__ float g_b[BT * Cc];
__device__ float g_q[BT * Cc];
__device__ float g_k[BT * Cc];
__device__ float g_v[BT * Cc];
__device__ float g_h[BT * HIDd];

// ---------------- depthwise conv along T (pad K/2), (B,T,C) layout ---------
__global__ void dwconv_kernel(const float* __restrict__ x,
                              const float* __restrict__ w,
                              const float* __restrict__ bias,
                              float* __restrict__ out) {
    int idx = blockIdx.x * 256 + threadIdx.x;
    if (idx >= BT * Cc) return;
    int c  = idx & (Cc - 1);
    int bt = idx >> 9;           // Cc == 512
    int t  = bt % Tt;
    int b  = bt / Tt;
    float acc = bias[c];
#pragma unroll
    for (int k = 0; k < Kk; k++) {
        int tt = t + k - Kk / 2;
        if (tt >= 0 && tt < Tt)
            acc = fmaf(x[((b * Tt + tt) << 9) + c], w[c * Kk + k], acc);
    }
    out[idx] = acc;
}

// ---------------- GEMM: C[M,N] = A[M,K] @ W[N,K]^T + bias, optional ReLU ---
// BM=64, BN=128, BK=16, 256 threads, 4x8 per-thread tile.
// M = 8000 (divisible by 64); N,K divisible by 128/16 -> no bounds checks.
template <int RELU>
__global__ void __launch_bounds__(256)
gemm_kernel(const float* __restrict__ A, const float* __restrict__ W,
            const float* __restrict__ bias, float* __restrict__ Cm,
            int N, int Kd) {
    __shared__ float As[16][65];
    __shared__ float Ws[16][129];

    int tid = threadIdx.x;
    int tx = tid & 15;           // 0..15 -> 8 columns each
    int ty = tid >> 4;           // 0..15 -> 4 rows each
    int rowBase = blockIdx.y * 64;
    int colBase = blockIdx.x * 128;

    float acc[4][8];
#pragma unroll
    for (int i = 0; i < 4; i++)
#pragma unroll
        for (int j = 0; j < 8; j++) acc[i][j] = 0.f;

    int am  = tid >> 2;          // 0..63
    int akq = (tid & 3) * 4;     // 0,4,8,12

    for (int k0 = 0; k0 < Kd; k0 += 16) {
        float4 av = *(const float4*)(A + (size_t)(rowBase + am) * Kd + k0 + akq);
        As[akq + 0][am] = av.x;
        As[akq + 1][am] = av.y;
        As[akq + 2][am] = av.z;
        As[akq + 3][am] = av.w;
#pragma unroll
        for (int i = 0; i < 2; i++) {
            int idx = tid + i * 256;
            int n   = idx >> 2;          // 0..127
            int kq  = (idx & 3) * 4;
            float4 wv = *(const float4*)(W + (size_t)(colBase + n) * Kd + k0 + kq);
            Ws[kq + 0][n] = wv.x;
            Ws[kq + 1][n] = wv.y;
            Ws[kq + 2][n] = wv.z;
            Ws[kq + 3][n] = wv.w;
        }
        __syncthreads();
#pragma unroll
        for (int kk = 0; kk < 16; kk++) {
            float a[4], wr[8];
#pragma unroll
            for (int i = 0; i < 4; i++) a[i] = As[kk][ty * 4 + i];
#pragma unroll
            for (int j = 0; j < 8; j++) wr[j] = Ws[kk][tx * 8 + j];
#pragma unroll
            for (int i = 0; i < 4; i++)
#pragma unroll
                for (int j = 0; j < 8; j++)
                    acc[i][j] = fmaf(a[i], wr[j], acc[i][j]);
        }
        __syncthreads();
    }

#pragma unroll
    for (int i = 0; i < 4; i++) {
        int m = rowBase + ty * 4 + i;
#pragma unroll
        for (int j = 0; j < 8; j++) {
            int n = colBase + tx * 8 + j;
            float v = acc[i][j] + bias[n];
            if (RELU) v = fmaxf(v, 0.f);
            Cm[(size_t)m * N + n] = v;
        }
    }
}

// ---------------- LayerNorm over last dim C (one block per row) ------------
__global__ void ln_kernel(const float* __restrict__ x,
                          const float* __restrict__ g,
                          const float* __restrict__ be,
                          float* __restrict__ out) {
    int row = blockIdx.x;
    int tid = threadIdx.x;   // 128
    const float* xr = x + (size_t)row * Cc;
    float v[4];
    float s = 0.f;
#pragma unroll
    for (int i = 0; i < 4; i++) { v[i] = xr[tid + i * 128]; s += v[i]; }
    __shared__ float red[128];
    red[tid] = s; __syncthreads();
    for (int st = 64; st > 0; st >>= 1) { if (tid < st) red[tid] += red[tid + st]; __syncthreads(); }
    float mean = red[0] * (1.f / Cc);
    __syncthreads();
    float vs = 0.f;
#pragma unroll
    for (int i = 0; i < 4; i++) { float d = v[i] - mean; vs += d * d; }
    red[tid] = vs; __syncthreads();
    for (int st = 64; st > 0; st >>= 1) { if (tid < st) red[tid] += red[tid + st]; __syncthreads(); }
    float inv = rsqrtf(red[0] * (1.f / Cc) + 1e-5f);
#pragma unroll
    for (int i = 0; i < 4; i++) {
        int c = tid + i * 128;
        out[(size_t)row * Cc + c] = (v[i] - mean) * inv * g[c] + be[c];
    }
}

// ---------------- causal softmax attention: one block per (q,h,b) ----------
__global__ void attn_kernel(const float* __restrict__ Q,
                            const float* __restrict__ Kp,
                            const float* __restrict__ V,
                            float* __restrict__ O) {
    int qt = blockIdx.x;
    int h  = blockIdx.y;
    int b  = blockIdx.z;
    int tid = threadIdx.x;  // 128
    __shared__ float qs[HD];
    __shared__ float sc[Tt];
    __shared__ float red[128];

    const float* qrow = Q + (size_t)(b * Tt + qt) * Cc + h * HD;
    if (tid < HD) qs[tid] = qrow[tid];
    __syncthreads();

    // scores for j <= qt
    for (int j = tid; j <= qt; j += 128) {
        const float4* kr = (const float4*)(Kp + (size_t)(b * Tt + j) * Cc + h * HD);
        float s = 0.f;
#pragma unroll
        for (int d4 = 0; d4 < HD / 4; d4++) {
            float4 kv = kr[d4];
            float4 qv = ((const float4*)qs)[d4];
            s += qv.x * kv.x + qv.y * kv.y + qv.z * kv.z + qv.w * kv.w;
        }
        sc[j] = s * SCALE;
    }
    __syncthreads();

    // max
    float mx = -1e30f;
    for (int j = tid; j <= qt; j += 128) mx = fmaxf(mx, sc[j]);
    red[tid] = mx; __syncthreads();
    for (int st = 64; st > 0; st >>= 1) { if (tid < st) red[tid] = fmaxf(red[tid], red[tid + st]); __syncthreads(); }
    mx = red[0]; __syncthreads();

    // exp + sum
    float sum = 0.f;
    for (int j = tid; j <= qt; j += 128) {
        float e = __expf(sc[j] - mx);
        sc[j] = e;
        sum += e;
    }
    red[tid] = sum; __syncthreads();
    for (int st = 64; st > 0; st >>= 1) { if (tid < st) red[tid] += red[tid + st]; __syncthreads(); }
    float inv = 1.f / red[0];
    __syncthreads();

    // out[d] = sum_j p_j * v[j,d]
    if (tid < HD) {
        float accv = 0.f;
        const float* vb = V + (size_t)b * Tt * Cc + h * HD + tid;
        for (int j = 0; j <= qt; j++)
            accv = fmaf(sc[j], vb[(size_t)j * Cc], accv);
        O[(size_t)(b * Tt + qt) * Cc + h * HD + tid] = accv * inv;
    }
}

// ---------------- host orchestration ---------------------------------------
extern "C" void kernel_launch(void* const* d_in, const int* in_sizes, int n_in,
                              void* d_out, int out_size) {
    (void)in_sizes; (void)n_in; (void)out_size;
    const float* x     = (const float*)d_in[0];
    const float* dw_w  = (const float*)d_in[1];
    const float* dw_b  = (const float*)d_in[2];
    const float* pw_w  = (const float*)d_in[3];
    const float* pw_b  = (const float*)d_in[4];
    const float* cln_g = (const float*)d_in[5];
    const float* cln_b = (const float*)d_in[6];
    const float* wq    = (const float*)d_in[7];
    const float* bq    = (const float*)d_in[8];
    const float* wk    = (const float*)d_in[9];
    const float* bk    = (const float*)d_in[10];
    const float* wv    = (const float*)d_in[11];
    const float* bv    = (const float*)d_in[12];
    const float* wo    = (const float*)d_in[13];
    const float* bo    = (const float*)d_in[14];
    const float* aln_g = (const float*)d_in[15];
    const float* aln_b = (const float*)d_in[16];
    const float* w1    = (const float*)d_in[17];
    const float* b1    = (const float*)d_in[18];
    const float* w2    = (const float*)d_in[19];
    const float* b2    = (const float*)d_in[20];
    const float* fln_g = (const float*)d_in[21];
    const float* fln_b = (const float*)d_in[22];
    float* out = (float*)d_out;

    float *a, *b, *q, *k, *v, *h;
    cudaGetSymbolAddress((void**)&a, g_a);
    cudaGetSymbolAddress((void**)&b, g_b);
    cudaGetSymbolAddress((void**)&q, g_q);
    cudaGetSymbolAddress((void**)&k, g_k);
    cudaGetSymbolAddress((void**)&v, g_v);
    cudaGetSymbolAddress((void**)&h, g_h);

    dim3 gemmN512(Cc / 128, BT / 64);     // (4, 125)
    dim3 gemmN2048(HIDd / 128, BT / 64);  // (16, 125)
    dim3 attnGrid(Tt, NHh, Bz);
    int dwBlocks = (BT * Cc + 255) / 256;

    const float* cur = x;
    for (int l = 0; l < Ll; l++) {
        // ---- conv block 0 ----
        const float* dww0 = dw_w  + (size_t)(l * NCb + 0) * Cc * Kk;
        const float* dwb0 = dw_b  + (size_t)(l * NCb + 0) * Cc;
        const float* pww0 = pw_w  + (size_t)(l * NCb + 0) * Cc * Cc;
        const float* pwb0 = pw_b  + (size_t)(l * NCb + 0) * Cc;
        const float* clg0 = cln_g + (size_t)(l * NCb + 0) * Cc;
        const float* clb0 = cln_b + (size_t)(l * NCb + 0) * Cc;
        dwconv_kernel<<<dwBlocks, 256>>>(cur, dww0, dwb0, a);
        gemm_kernel<0><<<gemmN512, 256>>>(a, pww0, pwb0, b, Cc, Cc);
        ln_kernel<<<BT, 128>>>(b, clg0, clb0, a);

        // ---- conv block 1 ----
        const float* dww1 = dw_w  + (size_t)(l * NCb + 1) * Cc * Kk;
        const float* dwb1 = dw_b  + (size_t)(l * NCb + 1) * Cc;
        const float* pww1 = pw_w  + (size_t)(l * NCb + 1) * Cc * Cc;
        const float* pwb1 = pw_b  + (size_t)(l * NCb + 1) * Cc;
        const float* clg1 = cln_g + (size_t)(l * NCb + 1) * Cc;
        const float* clb1 = cln_b + (size_t)(l * NCb + 1) * Cc;
        dwconv_kernel<<<dwBlocks, 256>>>(a, dww1, dwb1, b);
        gemm_kernel<0><<<gemmN512, 256>>>(b, pww1, pwb1, a, Cc, Cc);
        ln_kernel<<<BT, 128>>>(a, clg1, clb1, b);

        // ---- attention ----
        gemm_kernel<0><<<gemmN512, 256>>>(b, wq + (size_t)l * Cc * Cc, bq + (size_t)l * Cc, q, Cc, Cc);
        gemm_kernel<0><<<gemmN512, 256>>>(b, wk + (size_t)l * Cc * Cc, bk + (size_t)l * Cc, k, Cc, Cc);
        gemm_kernel<0><<<gemmN512, 256>>>(b, wv + (size_t)l * Cc * Cc, bv + (size_t)l * Cc, v, Cc, Cc);
        attn_kernel<<<attnGrid, 128>>>(q, k, v, a);
        gemm_kernel<0><<<gemmN512, 256>>>(a, wo + (size_t)l * Cc * Cc, bo + (size_t)l * Cc, b, Cc, Cc);
        ln_kernel<<<BT, 128>>>(b, aln_g + (size_t)l * Cc, aln_b + (size_t)l * Cc, a);

        // ---- FFN ----
        gemm_kernel<1><<<gemmN2048, 256>>>(a, w1 + (size_t)l * HIDd * Cc, b1 + (size_t)l * HIDd, h, HIDd, Cc);
        gemm_kernel<0><<<gemmN512, 256>>>(h, w2 + (size_t)l * Cc * HIDd, b2 + (size_t)l * Cc, b, Cc, HIDd);

        float* Y = out + (size_t)l * BT * Cc;
        ln_kernel<<<BT, 128>>>(b, fln_g + (size_t)l * Cc, fln_b + (size_t)l * Cc, Y);
        cur = Y;
    }
}

// round 3
// speedup vs baseline: 4.0883x; 4.0883x over previous
#include <cuda_runtime.h>
#include <math.h>
#include <stdint.h>

#define Bz   16
#define Tt   500
#define Cc   512
#define Kk   7
#define NHh  8
#define HD   64
#define HIDd 2048
#define Ll   3
#define NCb  2
#define BT   (Bz * Tt)
#define MT   8064            /* BT rounded up to 128 */
#define SCALE 0.125f

// ---------------- scratch (device globals; no runtime allocation) ----------
__device__ float g_a[MT * Cc];
__device__ float g_b[MT * Cc];
__device__ float g_q[MT * Cc];
__device__ float g_k[MT * Cc];
__device__ float g_v[MT * Cc];
__device__ float g_h[MT * HIDd];

// ---------------- small helpers -------------------------------------------
__device__ __forceinline__ uint32_t f2tf(float x) {
    uint32_t r;
    asm("cvt.rna.tf32.f32 %0, %1;" : "=r"(r) : "f"(x));
    return r;
}

__device__ __forceinline__ void mma_tf32(float* c, const uint32_t* a, const uint32_t* b) {
    asm volatile(
        "mma.sync.aligned.m16n8k8.row.col.f32.tf32.tf32.f32 "
        "{%0,%1,%2,%3}, {%4,%5,%6,%7}, {%8,%9}, {%0,%1,%2,%3};"
        : "+f"(c[0]), "+f"(c[1]), "+f"(c[2]), "+f"(c[3])
        : "r"(a[0]), "r"(a[1]), "r"(a[2]), "r"(a[3]), "r"(b[0]), "r"(b[1]));
}

__device__ __forceinline__ void cpa16(float* dst, const float* src) {
    unsigned d = (unsigned)__cvta_generic_to_shared(dst);
    asm volatile("cp.async.ca.shared.global [%0], [%1], 16;" :: "r"(d), "l"(src));
}

// ---------------- depthwise conv along T (pad K/2), (B,T,C) layout ---------
__global__ void dwconv_kernel(const float* __restrict__ x,
                              const float* __restrict__ w,
                              const float* __restrict__ bias,
                              float* __restrict__ out) {
    int idx = blockIdx.x * 256 + threadIdx.x;
    if (idx >= BT * Cc) return;
    int c  = idx & (Cc - 1);
    int bt = idx >> 9;
    int t  = bt % Tt;
    int b  = bt / Tt;
    float acc = bias[c];
#pragma unroll
    for (int k = 0; k < Kk; k++) {
        int tt = t + k - Kk / 2;
        if (tt >= 0 && tt < Tt)
            acc = fmaf(x[((b * Tt + tt) << 9) + c], w[c * Kk + k], acc);
    }
    out[idx] = acc;
}

// ---------------- TF32 tensor-core GEMM ------------------------------------
// C[M,N] = A[M,K] @ W[N,K]^T + bias (+optional ReLU)
// Block 128x128, BK=16, 256 threads (8 warps, warp tile 64x32), cp.async
// double buffer. grid.y covers padded MT; N,K multiples of 16.
#define GBM 128
#define GBN 128
#define GBK 16
#define GST 20   /* padded smem row stride in words */

template <int RELU>
__global__ void __launch_bounds__(256, 2)
gemm_tf32(const float* __restrict__ A, const float* __restrict__ W,
          const float* __restrict__ bias, float* __restrict__ Cm,
          int N_, int Kd) {
    __shared__ __align__(16) float As[2][GBM][GST];
    __shared__ __align__(16) float Bs[2][GBN][GST];

    int tid  = threadIdx.x;
    int lane = tid & 31;
    int wid  = tid >> 5;
    int g = lane >> 2;           // 0..7
    int t = lane & 3;            // 0..3
    int warpM = wid >> 2;        // 0..1
    int warpN = wid & 3;         // 0..3
    int rowBase = blockIdx.y * GBM;
    int colBase = blockIdx.x * GBN;

    // copy mapping: thread -> rows (cr, cr+64), 16B quad cq
    int cq = (tid & 3) * 4;      // 0,4,8,12  -> byte offset multiple of 16
    int cr = tid >> 2;           // 0..63
    const float* Aptr0 = A + (size_t)(rowBase + cr)      * Kd + cq;
    const float* Aptr1 = A + (size_t)(rowBase + cr + 64) * Kd + cq;
    const float* Wptr0 = W + (size_t)(colBase + cr)      * Kd + cq;
    const float* Wptr1 = W + (size_t)(colBase + cr + 64) * Kd + cq;

    float acc[4][4][4];
#pragma unroll
    for (int i = 0; i < 4; i++)
#pragma unroll
        for (int j = 0; j < 4; j++)
#pragma unroll
            for (int r = 0; r < 4; r++) acc[i][j][r] = 0.f;

    int KT = Kd / GBK;

    // prefetch tile 0
    cpa16(&As[0][cr][cq],      Aptr0);
    cpa16(&As[0][cr + 64][cq], Aptr1);
    cpa16(&Bs[0][cr][cq],      Wptr0);
    cpa16(&Bs[0][cr + 64][cq], Wptr1);
    asm volatile("cp.async.commit_group;");

    for (int kt = 0; kt < KT; kt++) {
        int buf = kt & 1;
        if (kt + 1 < KT) {
            int off = (kt + 1) * GBK;
            cpa16(&As[buf ^ 1][cr][cq],      Aptr0 + off);
            cpa16(&As[buf ^ 1][cr + 64][cq], Aptr1 + off);
            cpa16(&Bs[buf ^ 1][cr][cq],      Wptr0 + off);
            cpa16(&Bs[buf ^ 1][cr + 64][cq], Wptr1 + off);
            asm volatile("cp.async.commit_group;");
            asm volatile("cp.async.wait_group 1;");
        } else {
            asm volatile("cp.async.wait_group 0;");
        }
        __syncthreads();

#pragma unroll
        for (int ks = 0; ks < 2; ks++) {
            int k0 = ks * 8;
            uint32_t af[4][4], bf[4][2];
#pragma unroll
            for (int i = 0; i < 4; i++) {
                int r = warpM * 64 + i * 16;
                af[i][0] = f2tf(As[buf][r + g][k0 + t]);
                af[i][1] = f2tf(As[buf][r + g + 8][k0 + t]);
                af[i][2] = f2tf(As[buf][r + g][k0 + t + 4]);
                af[i][3] = f2tf(As[buf][r + g + 8][k0 + t + 4]);
            }
#pragma unroll
            for (int j = 0; j < 4; j++) {
                int n = warpN * 32 + j * 8 + g;
                bf[j][0] = f2tf(Bs[buf][n][k0 + t]);
                bf[j][1] = f2tf(Bs[buf][n][k0 + t + 4]);
            }
#pragma unroll
            for (int i = 0; i < 4; i++)
#pragma unroll
                for (int j = 0; j < 4; j++)
                    mma_tf32(acc[i][j], af[i], bf[j]);
        }
        __syncthreads();
    }

    // epilogue: c0 (g,2t) c1 (g,2t+1) c2 (g+8,2t) c3 (g+8,2t+1)
#pragma unroll
    for (int i = 0; i < 4; i++) {
        int m0 = rowBase + warpM * 64 + i * 16 + g;
#pragma unroll
        for (int j = 0; j < 4; j++) {
            int n = colBase + warpN * 32 + j * 8 + 2 * t;
            float b0 = bias[n], b1 = bias[n + 1];
            float v0 = acc[i][j][0] + b0;
            float v1 = acc[i][j][1] + b1;
            float v2 = acc[i][j][2] + b0;
            float v3 = acc[i][j][3] + b1;
            if (RELU) {
                v0 = fmaxf(v0, 0.f); v1 = fmaxf(v1, 0.f);
                v2 = fmaxf(v2, 0.f); v3 = fmaxf(v3, 0.f);
            }
            *(float2*)&Cm[(size_t)m0 * N_ + n]       = make_float2(v0, v1);
            *(float2*)&Cm[(size_t)(m0 + 8) * N_ + n] = make_float2(v2, v3);
        }
    }
}

// ---------------- LayerNorm over last dim C (one block per row) ------------
__global__ void ln_kernel(const float* __restrict__ x,
                          const float* __restrict__ g,
                          const float* __restrict__ be,
                          float* __restrict__ out) {
    int row = blockIdx.x;
    int tid = threadIdx.x;   // 128
    const float* xr = x + (size_t)row * Cc;
    float v[4];
    float s = 0.f;
#pragma unroll
    for (int i = 0; i < 4; i++) { v[i] = xr[tid + i * 128]; s += v[i]; }
    __shared__ float red[128];
    red[tid] = s; __syncthreads();
    for (int st = 64; st > 0; st >>= 1) { if (tid < st) red[tid] += red[tid + st]; __syncthreads(); }
    float mean = red[0] * (1.f / Cc);
    __syncthreads();
    float vs = 0.f;
#pragma unroll
    for (int i = 0; i < 4; i++) { float d = v[i] - mean; vs += d * d; }
    red[tid] = vs; __syncthreads();
    for (int st = 64; st > 0; st >>= 1) { if (tid < st) red[tid] += red[tid + st]; __syncthreads(); }
    float inv = rsqrtf(red[0] * (1.f / Cc) + 1e-5f);
#pragma unroll
    for (int i = 0; i < 4; i++) {
        int c = tid + i * 128;
        out[(size_t)row * Cc + c] = (v[i] - mean) * inv * g[c] + be[c];
    }
}

// ---------------- attention: 8 queries per block, shared K/V tiles ---------
#define QB 8
#define JT 64
__global__ void __launch_bounds__(256)
attn_kernel(const float* __restrict__ Q,
            const float* __restrict__ Kp,
            const float* __restrict__ V,
            float* __restrict__ O) {
    int qt0 = blockIdx.x * QB;
    int h   = blockIdx.y;
    int b   = blockIdx.z;
    int tid = threadIdx.x;   // 256
    int wid = tid >> 5;      // 0..7 -> query index within block
    int lane = tid & 31;

    __shared__ float qs[QB][HD + 1];
    __shared__ float kv[JT][HD + 1];
    __shared__ float sc[QB][512];

    int q = qt0 + wid;
    bool qvalid = q < Tt;

    // load Q rows
    for (int i = tid; i < QB * HD; i += 256) {
        int r = i >> 6, d = i & 63;
        int qq = qt0 + r;
        qs[r][d] = (qq < Tt) ? Q[(size_t)(b * Tt + qq) * Cc + h * HD + d] : 0.f;
    }
    __syncthreads();

    int qmax = min(qt0 + QB - 1, Tt - 1);
    int ntiles = qmax / JT + 1;

    // ---- phase 1: scores ----
    for (int jt = 0; jt < ntiles; jt++) {
        int j0 = jt * JT;
        for (int i = tid; i < JT * HD / 4; i += 256) {
            int r  = i >> 4;
            int dq = (i & 15) * 4;
            int j  = j0 + r;
            float4 kvv = (j < Tt)
                ? *(const float4*)&Kp[(size_t)(b * Tt + j) * Cc + h * HD + dq]
                : make_float4(0.f, 0.f, 0.f, 0.f);
            kv[r][dq + 0] = kvv.x;   // scalar smem stores: stride-65 rows are
            kv[r][dq + 1] = kvv.y;   // NOT 16B aligned, so no float4 here
            kv[r][dq + 2] = kvv.z;
            kv[r][dq + 3] = kvv.w;
        }
        __syncthreads();
        if (qvalid) {
            float s0 = 0.f, s1 = 0.f;
#pragma unroll 8
            for (int d = 0; d < HD; d++) {
                float qv = qs[wid][d];
                s0 = fmaf(qv, kv[lane][d], s0);
                s1 = fmaf(qv, kv[lane + 32][d], s1);
            }
            int j0l = j0 + lane;
            sc[wid][j0l]      = (j0l <= q)      ? s0 * SCALE : -1e30f;
            sc[wid][j0l + 32] = (j0l + 32 <= q) ? s1 * SCALE : -1e30f;
        }
        __syncthreads();
    }

    // ---- phase 2: softmax (warp-local per query) ----
    float inv = 0.f;
    if (qvalid) {
        float mx = -1e30f;
        for (int j = lane; j <= q; j += 32) mx = fmaxf(mx, sc[wid][j]);
#pragma unroll
        for (int o = 16; o > 0; o >>= 1) mx = fmaxf(mx, __shfl_xor_sync(0xffffffffu, mx, o));
        float sum = 0.f;
        for (int j = lane; j <= q; j += 32) {
            float e = __expf(sc[wid][j] - mx);
            sc[wid][j] = e;
            sum += e;
        }
#pragma unroll
        for (int o = 16; o > 0; o >>= 1) sum += __shfl_xor_sync(0xffffffffu, sum, o);
        inv = 1.f / sum;
    }

    // ---- phase 3: O = P @ V ----
    float acc0 = 0.f, acc1 = 0.f;
    for (int jt = 0; jt < ntiles; jt++) {
        int j0 = jt * JT;
        __syncthreads();
        for (int i = tid; i < JT * HD / 4; i += 256) {
            int r  = i >> 4;
            int dq = (i & 15) * 4;
            int j  = j0 + r;
            float4 vv = (j < Tt)
                ? *(const float4*)&V[(size_t)(b * Tt + j) * Cc + h * HD + dq]
                : make_float4(0.f, 0.f, 0.f, 0.f);
            kv[r][dq + 0] = vv.x;
            kv[r][dq + 1] = vv.y;
            kv[r][dq + 2] = vv.z;
            kv[r][dq + 3] = vv.w;
        }
        __syncthreads();
        if (qvalid) {
            int jend = min(q - j0, JT - 1);
            for (int jj = 0; jj <= jend; jj++) {
                float p = sc[wid][j0 + jj];
                acc0 = fmaf(p, kv[jj][lane], acc0);
                acc1 = fmaf(p, kv[jj][lane + 32], acc1);
            }
        }
    }
    if (qvalid) {
        O[(size_t)(b * Tt + q) * Cc + h * HD + lane]      = acc0 * inv;
        O[(size_t)(b * Tt + q) * Cc + h * HD + lane + 32] = acc1 * inv;
    }
}

// ---------------- host orchestration ---------------------------------------
extern "C" void kernel_launch(void* const* d_in, const int* in_sizes, int n_in,
                              void* d_out, int out_size) {
    (void)in_sizes; (void)n_in; (void)out_size;
    const float* x     = (const float*)d_in[0];
    const float* dw_w  = (const float*)d_in[1];
    const float* dw_b  = (const float*)d_in[2];
    const float* pw_w  = (const float*)d_in[3];
    const float* pw_b  = (const float*)d_in[4];
    const float* cln_g = (const float*)d_in[5];
    const float* cln_b = (const float*)d_in[6];
    const float* wq    = (const float*)d_in[7];
    const float* bq    = (const float*)d_in[8];
    const float* wk    = (const float*)d_in[9];
    const float* bk    = (const float*)d_in[10];
    const float* wv    = (const float*)d_in[11];
    const float* bv    = (const float*)d_in[12];
    const float* wo    = (const float*)d_in[13];
    const float* bo    = (const float*)d_in[14];
    const float* aln_g = (const float*)d_in[15];
    const float* aln_b = (const float*)d_in[16];
    const float* w1    = (const float*)d_in[17];
    const float* b1    = (const float*)d_in[18];
    const float* w2    = (const float*)d_in[19];
    const float* b2    = (const float*)d_in[20];
    const float* fln_g = (const float*)d_in[21];
    const float* fln_b = (const float*)d_in[22];
    float* out = (float*)d_out;

    float *a, *b, *q, *k, *v, *h;
    cudaGetSymbolAddress((void**)&a, g_a);
    cudaGetSymbolAddress((void**)&b, g_b);
    cudaGetSymbolAddress((void**)&q, g_q);
    cudaGetSymbolAddress((void**)&k, g_k);
    cudaGetSymbolAddress((void**)&v, g_v);
    cudaGetSymbolAddress((void**)&h, g_h);

    dim3 gemmN512(Cc / GBN, MT / GBM);     // (4, 63)
    dim3 gemmN2048(HIDd / GBN, MT / GBM);  // (16, 63)
    dim3 attnGrid((Tt + QB - 1) / QB, NHh, Bz);
    int dwBlocks = (BT * Cc + 255) / 256;

    const float* cur = x;
    for (int l = 0; l < Ll; l++) {
        // ---- conv block 0 ----
        const float* dww0 = dw_w  + (size_t)(l * NCb + 0) * Cc * Kk;
        const float* dwb0 = dw_b  + (size_t)(l * NCb + 0) * Cc;
        const float* pww0 = pw_w  + (size_t)(l * NCb + 0) * Cc * Cc;
        const float* pwb0 = pw_b  + (size_t)(l * NCb + 0) * Cc;
        const float* clg0 = cln_g + (size_t)(l * NCb + 0) * Cc;
        const float* clb0 = cln_b + (size_t)(l * NCb + 0) * Cc;
        dwconv_kernel<<<dwBlocks, 256>>>(cur, dww0, dwb0, a);
        gemm_tf32<0><<<gemmN512, 256>>>(a, pww0, pwb0, b, Cc, Cc);
        ln_kernel<<<BT, 128>>>(b, clg0, clb0, a);

        // ---- conv block 1 ----
        const float* dww1 = dw_w  + (size_t)(l * NCb + 1) * Cc * Kk;
        const float* dwb1 = dw_b  + (size_t)(l * NCb + 1) * Cc;
        const float* pww1 = pw_w  + (size_t)(l * NCb + 1) * Cc * Cc;
        const float* pwb1 = pw_b  + (size_t)(l * NCb + 1) * Cc;
        const float* clg1 = cln_g + (size_t)(l * NCb + 1) * Cc;
        const float* clb1 = cln_b + (size_t)(l * NCb + 1) * Cc;
        dwconv_kernel<<<dwBlocks, 256>>>(a, dww1, dwb1, b);
        gemm_tf32<0><<<gemmN512, 256>>>(b, pww1, pwb1, a, Cc, Cc);
        ln_kernel<<<BT, 128>>>(a, clg1, clb1, b);

        // ---- attention ----
        gemm_tf32<0><<<gemmN512, 256>>>(b, wq + (size_t)l * Cc * Cc, bq + (size_t)l * Cc, q, Cc, Cc);
        gemm_tf32<0><<<gemmN512, 256>>>(b, wk + (size_t)l * Cc * Cc, bk + (size_t)l * Cc, k, Cc, Cc);
        gemm_tf32<0><<<gemmN512, 256>>>(b, wv + (size_t)l * Cc * Cc, bv + (size_t)l * Cc, v, Cc, Cc);
        attn_kernel<<<attnGrid, 256>>>(q, k, v, a);
        gemm_tf32<0><<<gemmN512, 256>>>(a, wo + (size_t)l * Cc * Cc, bo + (size_t)l * Cc, b, Cc, Cc);
        ln_kernel<<<BT, 128>>>(b, aln_g + (size_t)l * Cc, aln_b + (size_t)l * Cc, a);

        // ---- FFN ----
        gemm_tf32<1><<<gemmN2048, 256>>>(a, w1 + (size_t)l * HIDd * Cc, b1 + (size_t)l * HIDd, h, HIDd, Cc);
        gemm_tf32<0><<<gemmN512, 256>>>(h, w2 + (size_t)l * Cc * HIDd, b2 + (size_t)l * Cc, b, Cc, HIDd);

        float* Y = out + (size_t)l * BT * Cc;
        ln_kernel<<<BT, 128>>>(b, fln_g + (size_t)l * Cc, fln_b + (size_t)l * Cc, Y);
        cur = Y;
    }
}